// round 12
// baseline (speedup 1.0000x reference)
#include <cuda_runtime.h>
#include <cuda_bf16.h>
#include <math.h>

// Problem constants
#define BB 64
#define SS 512
#define DD 1024
#define HH 1024
#define TT 9
#define MM (BB * SS)

// Time-chunking: chunk c covers rows [32c, 32c+31]
#define NC  16
#define LCH 32

// Scratch
__device__ float g_w12t[TT * DD];                 // W12 transposed: [t][k]
__device__ float g_b12[TT];
__device__ float g_M[(size_t)BB * NC * TT * TT];  // chunk transfer matrices (log)
__device__ float g_numP[BB * NC];
__device__ int   g_numF[BB * NC];
__device__ int   g_numL[BB * NC];
__device__ int   g_cnt[BB];

// ---------------------------------------------------------------------------
// Kernel A v5 (unchanged, measured 8.35us): W12 = W1@W2, padded smem staging.
// ---------------------------------------------------------------------------
#define SWP (HH + 4)

__global__ __launch_bounds__(256)
void w12_kernel(const float* __restrict__ W1,
                const float* __restrict__ b1,
                const float* __restrict__ W2,
                const float* __restrict__ b2,
                float* __restrict__ out) {
    if (blockIdx.x == 0) {
        if (threadIdx.x == 0) out[0] = 0.f;
        if (threadIdx.x < BB) g_cnt[threadIdx.x] = 0;
    }

    __shared__ float sw[TT * SWP];      // W2^T [t][h], padded (36.2 KB)

    const int tid = threadIdx.x;

    // stage W2^T: coalesced LDG, incremental (h,t), no div in loop.
    {
        int h = tid / TT;
        int t = tid - h * TT;
        #pragma unroll
        for (int i = 0; i < (HH * TT) / 256; i++) {
            sw[t * SWP + h] = W2[tid + i * 256];
            t += 4;
            h += 28;
            if (t >= TT) { t -= TT; h += 1; }
        }
    }
    __syncthreads();

    const int warp = tid >> 5;
    const int lane = tid & 31;
    const int row  = blockIdx.x * 8 + warp;
    if (row > DD) return;

    const float* arow = (row < DD) ? (W1 + (size_t)row * HH) : b1;

    float acc[TT];
    #pragma unroll
    for (int t = 0; t < TT; t++) acc[t] = 0.f;

    #pragma unroll
    for (int i = 0; i < HH / 128; i++) {
        const int h = i * 128 + lane * 4;
        const float4 a = *(const float4*)(arow + h);
        #pragma unroll
        for (int t = 0; t < TT; t++) {
            const float4 w = *(const float4*)(sw + t * SWP + h);
            acc[t] += a.x * w.x + a.y * w.y + a.z * w.z + a.w * w.w;
        }
    }

    float outv = 0.f;
    #pragma unroll
    for (int t = 0; t < TT; t++) {
        float v = acc[t];
        #pragma unroll
        for (int o = 16; o > 0; o >>= 1) v += __shfl_xor_sync(0xFFFFFFFFu, v, o);
        if (lane == t) outv = v;
    }
    if (lane < TT) {
        if (row < DD) g_w12t[lane * DD + row] = outv;
        else          g_b12[lane] = outv + b2[lane];
    }
}

// ---------------------------------------------------------------------------
// Fused kernel v2: logits (scalar FMA, double-buffered) + chunk scan +
// numerator + last-block combine. grid (NC, BB), 320 threads, 2 blocks/SM
// enforced (reg cap 102 — GEMV live set ~90).
//   warps 0-7 : 4 logit rows each (32 rows = chunk (b,c))
//   warps 0-8 : linear-domain scan, matrix row a = warp
//   warp 9    : chunk numerator partial; last block per batch combines
// ---------------------------------------------------------------------------
__global__ __launch_bounds__(320, 2)
void fused_kernel(const float* __restrict__ X,
                  const int* __restrict__ labels,
                  const int* __restrict__ mask,
                  const float* __restrict__ start_t,
                  const float* __restrict__ end_t,
                  const float* __restrict__ trans,
                  float* __restrict__ logits,
                  float* __restrict__ out) {
    const int c    = blockIdx.x;
    const int b    = blockIdx.y;
    const int warp = threadIdx.x >> 5;
    const int lane = threadIdx.x & 31;

    __shared__ float sw[TT * DD];      // W12T [t][k]  (36 KB)
    __shared__ float em_s[LCH][12];    // raw logits for this chunk's rows
    __shared__ float ee_s[LCH][12];    // exp(logits)
    __shared__ float str_s[TT * TT];   // trans
    __shared__ int   tg_s[LCH];
    __shared__ int   mk_s[LCH];

    // ---- cooperative loads ----
    {
        const float4* src = (const float4*)g_w12t;
        float4* dst = (float4*)sw;
        for (int i = threadIdx.x; i < TT * DD / 4; i += 320) dst[i] = src[i];
    }
    if (warp == 8) {
        tg_s[lane] = labels[b * SS + c * LCH + lane];
        mk_s[lane] = mask[b * SS + c * LCH + lane];
    }
    if (warp == 9) {
        for (int i = lane; i < TT * TT; i += 32) str_s[i] = trans[i];
    }
    __syncthreads();   // sw/tg/mk/str visible before any use

    // ---- phase 1: logits for rows [c*32 .. c*32+31] (warps 0-7, 4 rows) ----
    if (warp < 8) {
        const int lrow0 = warp * 4;
        const int grow0 = b * SS + c * LCH + lrow0;
        const float* xbase = X + (size_t)grow0 * DD + lane * 4;

        float acc[4][TT];
        #pragma unroll
        for (int r = 0; r < 4; r++)
            #pragma unroll
            for (int t = 0; t < TT; t++) acc[r][t] = 0.f;

        float4 xv[4];
        #pragma unroll
        for (int r = 0; r < 4; r++)
            xv[r] = *(const float4*)(xbase + (size_t)r * DD);

        for (int i = 0; i < DD / 128; i++) {
            const int k = i * 128 + lane * 4;
            float4 xn[4];
            if (i < DD / 128 - 1) {
                #pragma unroll
                for (int r = 0; r < 4; r++)
                    xn[r] = *(const float4*)(xbase + (size_t)r * DD + (i + 1) * 128);
            }
            #pragma unroll
            for (int t = 0; t < TT; t++) {
                const float4 wv = *(const float4*)(sw + t * DD + k);
                #pragma unroll
                for (int r = 0; r < 4; r++) {
                    acc[r][t] = fmaf(xv[r].x, wv.x, acc[r][t]);
                    acc[r][t] = fmaf(xv[r].y, wv.y, acc[r][t]);
                    acc[r][t] = fmaf(xv[r].z, wv.z, acc[r][t]);
                    acc[r][t] = fmaf(xv[r].w, wv.w, acc[r][t]);
                }
            }
            if (i < DD / 128 - 1) {
                #pragma unroll
                for (int r = 0; r < 4; r++) xv[r] = xn[r];
            }
        }

        #pragma unroll
        for (int r = 0; r < 4; r++) {
            float outv = 0.f;
            #pragma unroll
            for (int t = 0; t < TT; t++) {
                float v = acc[r][t];
                #pragma unroll
                for (int o = 16; o > 0; o >>= 1)
                    v += __shfl_xor_sync(0xFFFFFFFFu, v, o);
                if (lane == t) outv = v + g_b12[t];
            }
            if (lane < TT) {
                logits[(size_t)(grow0 + r) * TT + lane] = outv;
                em_s[lrow0 + r][lane] = outv;
                ee_s[lrow0 + r][lane] = __expf(outv);
            }
        }
    }
    __syncthreads();

    // ---- phase 2a: scan (warps 0-8; matrix row a = warp) ----
    if (warp <= 8) {
        const int a = warp;
        float Ecol[TT];
        {
            const int j = (lane < TT) ? lane : 0;
            #pragma unroll
            for (int i = 0; i < TT; i++) Ecol[i] = __expf(str_s[i * TT + j]);
        }

        float wvv   = (lane == a) ? 1.f : 0.f;
        float logsc = 0.f;
        const int sl0 = (c == 0) ? 1 : 0;

        for (int sl = sl0; sl < LCH; ++sl) {
            if (mk_s[sl] > 0) {
                const float e = (lane < TT) ? ee_s[sl][lane] : 0.f;
                float sum = 0.f;
                #pragma unroll
                for (int i = 0; i < TT; i++)
                    sum = fmaf(__shfl_sync(0xFFFFFFFFu, wvv, i), Ecol[i], sum);
                if (lane < TT) wvv = sum * e;

                const bool hi2 = __any_sync(0xFFFFFFFFu, wvv > 1e15f);
                const bool lo2 = !__any_sync(0xFFFFFFFFu, wvv > 1e-15f);
                if (hi2 || lo2) {
                    float mx = wvv;
                    #pragma unroll
                    for (int o = 16; o > 0; o >>= 1)
                        mx = fmaxf(mx, __shfl_xor_sync(0xFFFFFFFFu, mx, o));
                    wvv /= mx;
                    logsc += __logf(mx);
                }
            }
        }
        if (lane < TT) {
            const float v = (wvv > 0.f) ? (__logf(wvv) + logsc) : -1e30f;
            g_M[(((size_t)b * NC + c) * TT + a) * TT + lane] = v;
        }
        __threadfence();   // make logits + M writes device-visible
    }

    // ---- phase 2b: numerator partial (warp 9; 1 step per lane) ----
    if (warp == 9) {
        const bool valid = (c > 0) || (lane >= 1);
        const int  m = valid ? mk_s[lane] : 0;
        const int  t = tg_s[lane];

        float p = 0.f;
        if (m > 0) p = em_s[lane][t];

        int carry = (m > 0) ? t : -1;
        #pragma unroll
        for (int off = 1; off < 32; off <<= 1) {
            const int x = __shfl_up_sync(0xFFFFFFFFu, carry, off);
            if (lane >= off && carry < 0) carry = x;
        }
        const int pred = __shfl_up_sync(0xFFFFFFFFu, carry, 1);
        const bool isfirst = (m > 0) && (lane == 0 || pred < 0);
        if (m > 0 && lane > 0 && pred >= 0) p += str_s[pred * TT + t];

        #pragma unroll
        for (int o = 16; o > 0; o >>= 1)
            p += __shfl_xor_sync(0xFFFFFFFFu, p, o);

        const int lastTag = __shfl_sync(0xFFFFFFFFu, carry, 31);
        const unsigned bal = __ballot_sync(0xFFFFFFFFu, isfirst);
        int firstTag = -1;
        if (bal) firstTag = __shfl_sync(0xFFFFFFFFu, t, __ffs(bal) - 1);

        if (lane == 0) {
            g_numP[b * NC + c] = p;
            g_numF[b * NC + c] = firstTag;
            g_numL[b * NC + c] = lastTag;
            __threadfence();
        }
    }
    __syncthreads();

    // ---- phase 3: last block of this batch runs the combine ----
    if (warp == 9) {
        int old = 0;
        if (lane == 0) old = atomicAdd(&g_cnt[b], 1);
        old = __shfl_sync(0xFFFFFFFFu, old, 0);
        if (old != NC - 1) return;
        __threadfence();

        const float* em0 = logits + (size_t)b * SS * TT;
        const int tg0 = labels[b * SS];

        float Pv = (lane < NC) ? g_numP[b * NC + lane] : 0.f;
        int   Fv = (lane < NC) ? g_numF[b * NC + lane] : -1;
        int   Lv = (lane < NC) ? g_numL[b * NC + lane] : -1;

        float score = start_t[tg0] + em0[tg0];
        int prev = tg0;
        #pragma unroll
        for (int c2 = 0; c2 < NC; ++c2) {
            const float P = __shfl_sync(0xFFFFFFFFu, Pv, c2);
            const int   F = __shfl_sync(0xFFFFFFFFu, Fv, c2);
            const int   L = __shfl_sync(0xFFFFFFFFu, Lv, c2);
            if (F >= 0) {
                score += P + str_s[prev * TT + F];
                prev = L;
            }
        }
        score += end_t[prev];

        const float* Mb = g_M + (size_t)b * NC * TT * TT;
        float Mcur[TT], Mnxt[TT];
        #pragma unroll
        for (int i = 0; i < TT; i++)
            Mcur[i] = (lane < TT) ? Mb[(size_t)i * TT + lane] : -1e30f;

        float alpha = (lane < TT) ? (start_t[lane] + em0[lane]) : -1e30f;
        for (int c2 = 0; c2 < NC; ++c2) {
            if (c2 + 1 < NC) {
                const float* Mn = Mb + (size_t)(c2 + 1) * TT * TT;
                #pragma unroll
                for (int i = 0; i < TT; i++)
                    Mnxt[i] = (lane < TT) ? Mn[(size_t)i * TT + lane] : -1e30f;
            }
            float terms[TT];
            #pragma unroll
            for (int i = 0; i < TT; i++)
                terms[i] = __shfl_sync(0xFFFFFFFFu, alpha, i) + Mcur[i];
            float mx = terms[0];
            #pragma unroll
            for (int i = 1; i < TT; i++) mx = fmaxf(mx, terms[i]);
            float sum = 0.f;
            #pragma unroll
            for (int i = 0; i < TT; i++) sum += __expf(terms[i] - mx);
            if (lane < TT) alpha = mx + __logf(sum);
            #pragma unroll
            for (int i = 0; i < TT; i++) Mcur[i] = Mnxt[i];
        }

        const float v = (lane < TT) ? (alpha + end_t[lane]) : -1e30f;
        float mx = v;
        #pragma unroll
        for (int o = 16; o > 0; o >>= 1)
            mx = fmaxf(mx, __shfl_xor_sync(0xFFFFFFFFu, mx, o));
        float e = (lane < TT) ? __expf(v - mx) : 0.f;
        #pragma unroll
        for (int o = 16; o > 0; o >>= 1) e += __shfl_xor_sync(0xFFFFFFFFu, e, o);
        const float log_z = mx + __logf(e);

        if (lane == 0)
            atomicAdd(out, -(score - log_z) * (1.f / (float)BB));
    }
}

// ---------------------------------------------------------------------------
extern "C" void kernel_launch(void* const* d_in, const int* in_sizes, int n_in,
                              void* d_out, int out_size) {
    const float* input   = (const float*)d_in[0];
    const int*   labels  = (const int*)d_in[1];
    const int*   amask   = (const int*)d_in[2];
    const float* W1      = (const float*)d_in[3];
    const float* b1      = (const float*)d_in[4];
    const float* W2      = (const float*)d_in[5];
    const float* b2      = (const float*)d_in[6];
    const float* start_t = (const float*)d_in[7];
    const float* end_t   = (const float*)d_in[8];
    const float* trans   = (const float*)d_in[9];

    float* out    = (float*)d_out;
    float* logits = out + 1;   // layout: [loss, logits(B*S*T)]

    w12_kernel<<<129, 256>>>(W1, b1, W2, b2, out);

    dim3 grid(NC, BB);   // (16, 64)
    fused_kernel<<<grid, 320>>>(input, labels, amask, start_t, end_t, trans,
                                logits, out);
}

// round 13
// speedup vs baseline: 1.1639x; 1.1639x over previous
#include <cuda_runtime.h>
#include <cuda_bf16.h>
#include <math.h>

// Problem constants
#define BB 64
#define SS 512
#define DD 1024
#define HH 1024
#define TT 9
#define MM (BB * SS)

// Time-chunking: chunk c covers rows [32c, 32c+31]
#define NC  16
#define LCH 32

// Scratch
__device__ float g_w12t[TT * DD];                 // W12 transposed: [t][k]
__device__ float g_b12[TT];
__device__ float g_M[(size_t)BB * NC * TT * TT];  // chunk transfer matrices (log)
__device__ float g_numP[BB * NC];
__device__ int   g_numF[BB * NC];
__device__ int   g_numL[BB * NC];
__device__ int   g_cnt[BB];

// ---------------------------------------------------------------------------
// Kernel A v5 (measured 8.35us): W12 = W1@W2, padded smem staging.
// ---------------------------------------------------------------------------
#define SWP (HH + 4)

__global__ __launch_bounds__(256)
void w12_kernel(const float* __restrict__ W1,
                const float* __restrict__ b1,
                const float* __restrict__ W2,
                const float* __restrict__ b2,
                float* __restrict__ out) {
    if (blockIdx.x == 0) {
        if (threadIdx.x == 0) out[0] = 0.f;
        if (threadIdx.x < BB) g_cnt[threadIdx.x] = 0;
    }

    __shared__ float sw[TT * SWP];      // W2^T [t][h], padded (36.2 KB)

    const int tid = threadIdx.x;

    // stage W2^T: coalesced LDG, incremental (h,t), no div in loop.
    {
        int h = tid / TT;
        int t = tid - h * TT;
        #pragma unroll
        for (int i = 0; i < (HH * TT) / 256; i++) {
            sw[t * SWP + h] = W2[tid + i * 256];
            t += 4;
            h += 28;
            if (t >= TT) { t -= TT; h += 1; }
        }
    }
    __syncthreads();

    const int warp = tid >> 5;
    const int lane = tid & 31;
    const int row  = blockIdx.x * 8 + warp;
    if (row > DD) return;

    const float* arow = (row < DD) ? (W1 + (size_t)row * HH) : b1;

    float acc[TT];
    #pragma unroll
    for (int t = 0; t < TT; t++) acc[t] = 0.f;

    #pragma unroll
    for (int i = 0; i < HH / 128; i++) {
        const int h = i * 128 + lane * 4;
        const float4 a = *(const float4*)(arow + h);
        #pragma unroll
        for (int t = 0; t < TT; t++) {
            const float4 w = *(const float4*)(sw + t * SWP + h);
            acc[t] += a.x * w.x + a.y * w.y + a.z * w.z + a.w * w.w;
        }
    }

    float outv = 0.f;
    #pragma unroll
    for (int t = 0; t < TT; t++) {
        float v = acc[t];
        #pragma unroll
        for (int o = 16; o > 0; o >>= 1) v += __shfl_xor_sync(0xFFFFFFFFu, v, o);
        if (lane == t) outv = v;
    }
    if (lane < TT) {
        if (row < DD) g_w12t[lane * DD + row] = outv;
        else          g_b12[lane] = outv + b2[lane];
    }
}

// ---------------------------------------------------------------------------
// Kernel B v4: logits[M,9] = X[M,1024] @ W12 + b12
// 512 threads, 2 rows/warp, 64-reg cap -> 32 warps/SM (issue-bound fix).
// ---------------------------------------------------------------------------
#define RPW 2

__global__ __launch_bounds__(512, 2)
void logits_kernel(const float* __restrict__ X,
                   float* __restrict__ logits) {
    __shared__ float sw[TT * DD];   // 36 KB

    {
        const float4* src = (const float4*)g_w12t;
        float4* dst = (float4*)sw;
        for (int i = threadIdx.x; i < TT * DD / 4; i += 512) dst[i] = src[i];
    }
    __syncthreads();

    const int warp = threadIdx.x >> 5;
    const int lane = threadIdx.x & 31;
    const int row0 = (blockIdx.x * 16 + warp) * RPW;
    const float* xbase = X + (size_t)row0 * DD + lane * 4;

    float acc[RPW][TT];
    #pragma unroll
    for (int r = 0; r < RPW; r++)
        #pragma unroll
        for (int t = 0; t < TT; t++) acc[r][t] = 0.f;

    float4 xv[RPW];
    #pragma unroll
    for (int r = 0; r < RPW; r++)
        xv[r] = *(const float4*)(xbase + (size_t)r * DD);

    for (int i = 0; i < DD / 128; i++) {
        const int k = i * 128 + lane * 4;
        float4 xn[RPW];
        if (i < DD / 128 - 1) {
            #pragma unroll
            for (int r = 0; r < RPW; r++)
                xn[r] = *(const float4*)(xbase + (size_t)r * DD + (i + 1) * 128);
        }
        #pragma unroll
        for (int t = 0; t < TT; t++) {
            const float4 wv = *(const float4*)(sw + t * DD + k);
            #pragma unroll
            for (int r = 0; r < RPW; r++) {
                acc[r][t] = fmaf(xv[r].x, wv.x, acc[r][t]);
                acc[r][t] = fmaf(xv[r].y, wv.y, acc[r][t]);
                acc[r][t] = fmaf(xv[r].z, wv.z, acc[r][t]);
                acc[r][t] = fmaf(xv[r].w, wv.w, acc[r][t]);
            }
        }
        if (i < DD / 128 - 1) {
            #pragma unroll
            for (int r = 0; r < RPW; r++) xv[r] = xn[r];
        }
    }

    #pragma unroll
    for (int r = 0; r < RPW; r++) {
        const int row = row0 + r;
        float outv = 0.f;
        #pragma unroll
        for (int t = 0; t < TT; t++) {
            float v = acc[r][t];
            #pragma unroll
            for (int o = 16; o > 0; o >>= 1) v += __shfl_xor_sync(0xFFFFFFFFu, v, o);
            if (lane == t) outv = v + g_b12[t];
        }
        if (lane < TT) logits[(size_t)row * TT + lane] = outv;
    }
}

// ---------------------------------------------------------------------------
// Kernel C: scan + numerator + last-block combine. grid (NC, BB), 320 thr.
// ---------------------------------------------------------------------------
__global__ __launch_bounds__(320)
void scan_kernel(const int* __restrict__ labels,
                 const int* __restrict__ mask,
                 const float* __restrict__ start_t,
                 const float* __restrict__ end_t,
                 const float* __restrict__ trans,
                 const float* __restrict__ logits,
                 float* __restrict__ out) {
    const int c    = blockIdx.x;
    const int b    = blockIdx.y;
    const int warp = threadIdx.x >> 5;
    const int lane = threadIdx.x & 31;

    __shared__ float ee_s[LCH][12];
    __shared__ float str_s[TT * TT];
    __shared__ int   tg_s[LCH];
    __shared__ int   mk_s[LCH];

    const float* emc = logits + ((size_t)b * SS + c * LCH) * TT;

    if (threadIdx.x < LCH * TT) {
        const int row = threadIdx.x / TT;
        const int t   = threadIdx.x % TT;
        ee_s[row][t] = __expf(emc[row * TT + t]);
    }
    if (warp == 9) {
        if (lane < LCH) {
            tg_s[lane] = labels[b * SS + c * LCH + lane];
            mk_s[lane] = mask[b * SS + c * LCH + lane];
        }
    }
    if (threadIdx.x >= 288 && threadIdx.x < 288 + 27) {
        const int i = threadIdx.x - 288;
        str_s[i * 3 + 0] = trans[i * 3 + 0];
        str_s[i * 3 + 1] = trans[i * 3 + 1];
        str_s[i * 3 + 2] = trans[i * 3 + 2];
    }
    __syncthreads();

    // ---- scan (warps 0-8; matrix row a = warp) ----
    if (warp <= 8) {
        const int a = warp;
        float Ecol[TT];
        {
            const int j = (lane < TT) ? lane : 0;
            #pragma unroll
            for (int i = 0; i < TT; i++) Ecol[i] = __expf(str_s[i * TT + j]);
        }

        float wvv   = (lane == a) ? 1.f : 0.f;
        float logsc = 0.f;
        const int sl0 = (c == 0) ? 1 : 0;

        for (int sl = sl0; sl < LCH; ++sl) {
            if (mk_s[sl] > 0) {
                const float e = (lane < TT) ? ee_s[sl][lane] : 0.f;
                float sum = 0.f;
                #pragma unroll
                for (int i = 0; i < TT; i++)
                    sum = fmaf(__shfl_sync(0xFFFFFFFFu, wvv, i), Ecol[i], sum);
                if (lane < TT) wvv = sum * e;

                const bool hi = __any_sync(0xFFFFFFFFu, wvv > 1e15f);
                const bool lo = !__any_sync(0xFFFFFFFFu, wvv > 1e-15f);
                if (hi || lo) {
                    float mx = wvv;
                    #pragma unroll
                    for (int o = 16; o > 0; o >>= 1)
                        mx = fmaxf(mx, __shfl_xor_sync(0xFFFFFFFFu, mx, o));
                    wvv /= mx;
                    logsc += __logf(mx);
                }
            }
        }
        if (lane < TT) {
            const float v = (wvv > 0.f) ? (__logf(wvv) + logsc) : -1e30f;
            g_M[(((size_t)b * NC + c) * TT + a) * TT + lane] = v;
        }
        __threadfence();
    }

    // ---- numerator partial (warp 9) ----
    if (warp == 9) {
        const bool valid = (c > 0) || (lane >= 1);
        const int  m = valid ? mk_s[lane] : 0;
        const int  t = tg_s[lane];

        float p = 0.f;
        if (m > 0) p = emc[lane * TT + t];

        int carry = (m > 0) ? t : -1;
        #pragma unroll
        for (int off = 1; off < 32; off <<= 1) {
            const int x = __shfl_up_sync(0xFFFFFFFFu, carry, off);
            if (lane >= off && carry < 0) carry = x;
        }
        const int pred = __shfl_up_sync(0xFFFFFFFFu, carry, 1);
        const bool isfirst = (m > 0) && (lane == 0 || pred < 0);
        if (m > 0 && lane > 0 && pred >= 0) p += str_s[pred * TT + t];

        #pragma unroll
        for (int o = 16; o > 0; o >>= 1)
            p += __shfl_xor_sync(0xFFFFFFFFu, p, o);

        const int lastTag = __shfl_sync(0xFFFFFFFFu, carry, 31);
        const unsigned bal = __ballot_sync(0xFFFFFFFFu, isfirst);
        int firstTag = -1;
        if (bal) firstTag = __shfl_sync(0xFFFFFFFFu, t, __ffs(bal) - 1);

        if (lane == 0) {
            g_numP[b * NC + c] = p;
            g_numF[b * NC + c] = firstTag;
            g_numL[b * NC + c] = lastTag;
            __threadfence();
        }
    }
    __syncthreads();

    // ---- last block of this batch runs the combine ----
    if (warp == 9) {
        int old = 0;
        if (lane == 0) old = atomicAdd(&g_cnt[b], 1);
        old = __shfl_sync(0xFFFFFFFFu, old, 0);
        if (old != NC - 1) return;
        __threadfence();

        const float* em0 = logits + (size_t)b * SS * TT;
        const int tg0 = labels[b * SS];

        float Pv = (lane < NC) ? g_numP[b * NC + lane] : 0.f;
        int   Fv = (lane < NC) ? g_numF[b * NC + lane] : -1;
        int   Lv = (lane < NC) ? g_numL[b * NC + lane] : -1;

        float score = start_t[tg0] + em0[tg0];
        int prev = tg0;
        #pragma unroll
        for (int c2 = 0; c2 < NC; ++c2) {
            const float P = __shfl_sync(0xFFFFFFFFu, Pv, c2);
            const int   F = __shfl_sync(0xFFFFFFFFu, Fv, c2);
            const int   L = __shfl_sync(0xFFFFFFFFu, Lv, c2);
            if (F >= 0) {
                score += P + str_s[prev * TT + F];
                prev = L;
            }
        }
        score += end_t[prev];

        const float* Mb = g_M + (size_t)b * NC * TT * TT;
        float Mcur[TT], Mnxt[TT];
        #pragma unroll
        for (int i = 0; i < TT; i++)
            Mcur[i] = (lane < TT) ? Mb[(size_t)i * TT + lane] : -1e30f;

        float alpha = (lane < TT) ? (start_t[lane] + em0[lane]) : -1e30f;
        for (int c2 = 0; c2 < NC; ++c2) {
            if (c2 + 1 < NC) {
                const float* Mn = Mb + (size_t)(c2 + 1) * TT * TT;
                #pragma unroll
                for (int i = 0; i < TT; i++)
                    Mnxt[i] = (lane < TT) ? Mn[(size_t)i * TT + lane] : -1e30f;
            }
            float terms[TT];
            #pragma unroll
            for (int i = 0; i < TT; i++)
                terms[i] = __shfl_sync(0xFFFFFFFFu, alpha, i) + Mcur[i];
            float mx = terms[0];
            #pragma unroll
            for (int i = 1; i < TT; i++) mx = fmaxf(mx, terms[i]);
            float sum = 0.f;
            #pragma unroll
            for (int i = 0; i < TT; i++) sum += __expf(terms[i] - mx);
            if (lane < TT) alpha = mx + __logf(sum);
            #pragma unroll
            for (int i = 0; i < TT; i++) Mcur[i] = Mnxt[i];
        }

        const float v = (lane < TT) ? (alpha + end_t[lane]) : -1e30f;
        float mx = v;
        #pragma unroll
        for (int o = 16; o > 0; o >>= 1)
            mx = fmaxf(mx, __shfl_xor_sync(0xFFFFFFFFu, mx, o));
        float e = (lane < TT) ? __expf(v - mx) : 0.f;
        #pragma unroll
        for (int o = 16; o > 0; o >>= 1) e += __shfl_xor_sync(0xFFFFFFFFu, e, o);
        const float log_z = mx + __logf(e);

        if (lane == 0)
            atomicAdd(out, -(score - log_z) * (1.f / (float)BB));
    }
}

// ---------------------------------------------------------------------------
extern "C" void kernel_launch(void* const* d_in, const int* in_sizes, int n_in,
                              void* d_out, int out_size) {
    const float* input   = (const float*)d_in[0];
    const int*   labels  = (const int*)d_in[1];
    const int*   amask   = (const int*)d_in[2];
    const float* W1      = (const float*)d_in[3];
    const float* b1      = (const float*)d_in[4];
    const float* W2      = (const float*)d_in[5];
    const float* b2      = (const float*)d_in[6];
    const float* start_t = (const float*)d_in[7];
    const float* end_t   = (const float*)d_in[8];
    const float* trans   = (const float*)d_in[9];

    float* out    = (float*)d_out;
    float* logits = out + 1;   // layout: [loss, logits(B*S*T)]

    w12_kernel<<<129, 256>>>(W1, b1, W2, b2, out);

    // 32768 rows / (16 warps * 2 rows) = 1024 blocks
    logits_kernel<<<MM / (16 * RPW), 512>>>(input, logits);

    dim3 grid(NC, BB);   // (16, 64)
    scan_kernel<<<grid, 320>>>(labels, amask, start_t, end_t, trans,
                               logits, out);
}